// round 14
// baseline (speedup 1.0000x reference)
#include <cuda_runtime.h>

// SSD post-processing: decode + per-class greedy NMS.
//   loc_data  [8, 3000, 4]  f32
//   conf_data [8, 3000, 21] f32
//   priors    [3000, 4]     f32
//   out       [8, 21, 200, 5] f32  (score, x1, y1, x2, y2), zero-padded
//
// One CTA per (class, batch), grid (21, 8), 256 threads.
// R13 kernel (193us) with EXACTLY ONE change: Phase A's accepted-list test is
// unrolled by 4 with a grouped early-out (4 independent LDS.128 pipeline per
// branch instead of a dependent load->branch chain per accepted box).
// Grouping does not change the final alive decision => bit-identical output.

#define NP    3000
#define NPAD  4096
#define NC    21
#define TOPK  200
#define NT    256
#define NWARP (NT / 32)
#define EPT   (NPAD / NT)                 // 16 keys per thread
#define SW(i) ((i) ^ (((i) >> 4) & 15))   // bank swizzle for u64 keys[]

typedef unsigned long long ull;

__device__ __forceinline__ void cexch(ull& a, ull& b, bool desc) {
    if (desc ? (a < b) : (a > b)) { ull t = a; a = b; b = t; }
}

// reference-exact IoU (no FMA contraction)
__device__ __forceinline__ float iou_rn(float ax1, float ay1, float ax2, float ay2, float aa,
                                        float bx1, float by1, float bx2, float by2, float ba)
{
    float ltx = fmaxf(ax1, bx1);
    float lty = fmaxf(ay1, by1);
    float rbx = fminf(ax2, bx2);
    float rby = fminf(ay2, by2);
    float wx  = fmaxf(__fsub_rn(rbx, ltx), 0.0f);
    float wy  = fmaxf(__fsub_rn(rby, lty), 0.0f);
    float inter = __fmul_rn(wx, wy);
    float uni   = __fsub_rn(__fadd_rn(aa, ba), inter);
    return __fdiv_rn(inter, fmaxf(uni, 1e-12f));
}

__global__ __launch_bounds__(NT, 2) void ssd_post_kernel(
    const float* __restrict__ loc,
    const float* __restrict__ conf,
    const float* __restrict__ priors,
    float* __restrict__ out)
{
    __shared__ ull    keys[NPAD];     // 32 KB
    __shared__ float4 sbox[NT];       // tile candidate boxes
    __shared__ float  sare[NT];       // tile candidate areas
    __shared__ float4 abox[TOPK];     // accepted boxes
    __shared__ float  aare[TOPK];     // accepted areas
    __shared__ int    salv[NWARP];    // per-warp alive ballots
    __shared__ int    s_nvalid;

    const int c    = blockIdx.x;
    const int b    = blockIdx.y;
    const int tid  = threadIdx.x;
    const int lane = tid & 31;
    const int wix  = tid >> 5;

    float* outp = out + (size_t)(b * NC + c) * (TOPK * 5);
    for (int k = tid; k < TOPK * 5; k += NT) outp[k] = 0.0f;
    if (c == 0) return;  // background class: zeros only

    if (tid == 0) s_nvalid = 0;
    __syncthreads();

    // ---- build sort keys: (sortable(score) << 32) | ~idx  (stable desc) ----
    const float* confb = conf + (size_t)b * NP * NC + c;
    int myValid = 0;
    #pragma unroll
    for (int w = 0; w < EPT; ++w) {
        int p = tid + w * NT;
        ull key = 0ULL;                               // padding: below everything
        if (p < NP) {
            float s = confb[(size_t)p * NC];
            bool v = (s > 0.01f);
            myValid += v ? 1 : 0;
            if (!v) s = __int_as_float(0xff800000);   // -inf: sorts after valid
            unsigned u = __float_as_uint(s);
            u = (u & 0x80000000u) ? ~u : (u | 0x80000000u);
            key = ((ull)u << 32) | (unsigned)(~p);
        }
        keys[SW(p)] = key;
    }
    #pragma unroll
    for (int o = 16; o > 0; o >>= 1)
        myValid += __shfl_down_sync(0xffffffffu, myValid, o);
    if (lane == 0 && myValid) atomicAdd(&s_nvalid, myValid);
    __syncthreads();

    // ---- bitonic sort, descending (register-fused) ----
    // fused register-local stages k = 2..16 (all strides < 16)
    {
        const int base = tid * EPT;
        ull r[EPT];
        #pragma unroll
        for (int m = 0; m < EPT; ++m) r[m] = keys[SW(base + m)];
        #pragma unroll
        for (int k = 2; k <= 16; k <<= 1) {
            #pragma unroll
            for (int j = k >> 1; j >= 1; j >>= 1) {
                #pragma unroll
                for (int m = 0; m < EPT; ++m)
                    if (!(m & j))
                        cexch(r[m], r[m | j], ((base + m) & k) == 0);
            }
        }
        #pragma unroll
        for (int m = 0; m < EPT; ++m) keys[SW(base + m)] = r[m];
    }
    __syncthreads();

    for (int k = 32; k <= NPAD; k <<= 1) {
        // smem substages: strides >= 16, pair-expanded (all threads active)
        for (int j = k >> 1; j >= 16; j >>= 1) {
            #pragma unroll
            for (int w = 0; w < NPAD / (2 * NT); ++w) {
                int p   = tid + w * NT;
                int i   = ((p & ~(j - 1)) << 1) | (p & (j - 1));
                int ixj = i | j;
                ull a  = keys[SW(i)];
                ull bb = keys[SW(ixj)];
                if (((i & k) == 0) ? (a < bb) : (a > bb)) {
                    keys[SW(i)] = bb; keys[SW(ixj)] = a;
                }
            }
            __syncthreads();
        }
        // register-local tail: strides 8,4,2,1 (uniform direction per thread)
        {
            const int  base = tid * EPT;
            const bool desc = ((base & k) == 0);
            ull r[EPT];
            #pragma unroll
            for (int m = 0; m < EPT; ++m) r[m] = keys[SW(base + m)];
            #pragma unroll
            for (int j = 8; j >= 1; j >>= 1) {
                #pragma unroll
                for (int m = 0; m < EPT; ++m)
                    if (!(m & j)) cexch(r[m], r[m | j], desc);
            }
            #pragma unroll
            for (int m = 0; m < EPT; ++m) keys[SW(base + m)] = r[m];
        }
        __syncthreads();
    }

    // ---- tiled candidate-driven NMS ----
    const int nvalid = s_nvalid;   // valid candidates form the sorted prefix
    const float* locb = loc + (size_t)b * NP * 4;

    int cnt = 0;                   // uniform register across all threads

    for (int tb = 0; tb < nvalid && cnt < TOPK; tb += NT) {
        const int j = tb + tid;
        ull key = keys[SW(j)];
        bool myAlive = (j < nvalid) && ((key >> 63) != 0ULL);

        // decode my candidate (exact reference op order) into regs + tile smem
        float mx1 = 0.f, my1 = 0.f, mx2 = 0.f, my2 = 0.f, mar = 0.f, ms = 0.f;
        if (myAlive) {
            int idx = (int)(~(unsigned)key);
            ms = __uint_as_float((unsigned)(key >> 32) & 0x7FFFFFFFu);
            float4 l  = *(const float4*)(locb + (size_t)idx * 4);
            float4 pr = *(const float4*)(priors + (size_t)idx * 4);
            float cx = __fadd_rn(pr.x, __fmul_rn(__fmul_rn(l.x, 0.1f), pr.z));
            float cy = __fadd_rn(pr.y, __fmul_rn(__fmul_rn(l.y, 0.1f), pr.w));
            float w  = __fmul_rn(pr.z, expf(__fmul_rn(l.z, 0.2f)));
            float hh = __fmul_rn(pr.w, expf(__fmul_rn(l.w, 0.2f)));
            mx1 = __fsub_rn(cx, __fmul_rn(0.5f, w));
            my1 = __fsub_rn(cy, __fmul_rn(0.5f, hh));
            mx2 = __fadd_rn(mx1, w);
            my2 = __fadd_rn(my1, hh);
            mar = __fmul_rn(__fsub_rn(mx2, mx1), __fsub_rn(my2, my1));
            sbox[tid] = make_float4(mx1, my1, mx2, my2);
            sare[tid] = mar;
        }

        // Phase A: test vs committed accepted list, unroll-4 grouped early-out
        // (4 independent LDS.128 pipeline per branch; same final decision)
        if (myAlive) {
            bool ov = false;
            int q = 0;
            for (; q + 4 <= cnt; q += 4) {
                float4 a0 = abox[q+0]; float4 a1 = abox[q+1];
                float4 a2 = abox[q+2]; float4 a3 = abox[q+3];
                float i0 = iou_rn(mx1,my1,mx2,my2,mar, a0.x,a0.y,a0.z,a0.w, aare[q+0]);
                float i1 = iou_rn(mx1,my1,mx2,my2,mar, a1.x,a1.y,a1.z,a1.w, aare[q+1]);
                float i2 = iou_rn(mx1,my1,mx2,my2,mar, a2.x,a2.y,a2.z,a2.w, aare[q+2]);
                float i3 = iou_rn(mx1,my1,mx2,my2,mar, a3.x,a3.y,a3.z,a3.w, aare[q+3]);
                if ((i0 > 0.45f) | (i1 > 0.45f) | (i2 > 0.45f) | (i3 > 0.45f)) { ov = true; break; }
            }
            if (!ov) {
                for (; q < cnt; ++q) {
                    float4 ab = abox[q];
                    if (iou_rn(mx1, my1, mx2, my2, mar,
                               ab.x, ab.y, ab.z, ab.w, aare[q]) > 0.45f) { ov = true; break; }
                }
            }
            myAlive = !ov;
        }
        unsigned wm = __ballot_sync(0xffffffffu, myAlive);
        if (lane == 0) salv[wix] = (int)wm;
        __syncthreads();   // publish sbox/sare/salv for the accept loop

        // Serial accept loop: ONE barrier per accept.
        // Every warp redundantly finds the first alive candidate from the 8
        // published ballot words (LDS+ballot+shfl+ffs). All branch decisions
        // read only barrier-published state => uniform.
        while (true) {
            int wv = (lane < NWARP) ? salv[lane] : 0;
            unsigned nz = __ballot_sync(0xffffffffu, wv != 0);
            if (nz == 0) break;                      // tile exhausted (uniform)
            int fw   = __ffs(nz) - 1;
            int word = __shfl_sync(0xffffffffu, wv, fw);
            int i    = (fw << 5) + __ffs(word) - 1;  // first alive candidate

            if (tid == i) {
                // accept my candidate as kept #cnt
                abox[cnt] = make_float4(mx1, my1, mx2, my2);
                aare[cnt] = mar;
                float* o = outp + cnt * 5;
                o[0] = ms; o[1] = mx1; o[2] = my1; o[3] = mx2; o[4] = my2;
                myAlive = false;
            } else if (myAlive) {
                // all alive threads have tid > i (i is the first alive)
                float4 ib = sbox[i];
                float ii = iou_rn(mx1, my1, mx2, my2, mar,
                                  ib.x, ib.y, ib.z, ib.w, sare[i]);
                if (ii > 0.45f) myAlive = false;
            }
            unsigned wm2 = __ballot_sync(0xffffffffu, myAlive);
            if (lane == 0) salv[wix] = (int)wm2;
            cnt++;                                   // uniform
            __syncthreads();                         // publish salv/abox/aare
            if (cnt >= TOPK) break;                  // uniform
        }
        __syncthreads();   // reconverge before next tile overwrites sbox/salv
    }
}

extern "C" void kernel_launch(void* const* d_in, const int* in_sizes, int n_in,
                              void* d_out, int out_size)
{
    const float* loc = nullptr;
    const float* conf = nullptr;
    const float* priors = nullptr;
    for (int i = 0; i < n_in; i++) {
        if (in_sizes[i] == 8 * NP * 4)       loc    = (const float*)d_in[i];
        else if (in_sizes[i] == 8 * NP * NC) conf   = (const float*)d_in[i];
        else if (in_sizes[i] == NP * 4)      priors = (const float*)d_in[i];
    }
    float* out = (float*)d_out;

    dim3 grid(NC, 8);
    ssd_post_kernel<<<grid, NT>>>(loc, conf, priors, out);
}

// round 16
// speedup vs baseline: 1.6366x; 1.6366x over previous
#include <cuda_runtime.h>

// SSD post-processing: decode + per-class greedy NMS.
//   loc_data  [8, 3000, 4]  f32
//   conf_data [8, 3000, 21] f32
//   priors    [3000, 4]     f32
//   out       [8, 21, 200, 5] f32  (score, x1, y1, x2, y2), zero-padded
//
// One CTA per (class, batch), grid (21, 8), 256 threads.
// R13 kernel (193us) with EXACTLY ONE change: Phase A is branchless and
// pipelined (ov |= over the accepted list, unroll 4, LDS.128s overlap) with a
// warp-granularity early-out (__all_sync vote every 16 boxes). Per-lane
// early-out only ever helped when ALL 32 lanes exited -- the vote captures
// exactly that case without serializing each iteration behind a branch.
// Boolean-OR over the same set => bit-identical output.

#define NP    3000
#define NPAD  4096
#define NC    21
#define TOPK  200
#define NT    256
#define NWARP (NT / 32)
#define EPT   (NPAD / NT)                 // 16 keys per thread
#define SW(i) ((i) ^ (((i) >> 4) & 15))   // bank swizzle for u64 keys[]

typedef unsigned long long ull;

__device__ __forceinline__ void cexch(ull& a, ull& b, bool desc) {
    if (desc ? (a < b) : (a > b)) { ull t = a; a = b; b = t; }
}

// reference-exact IoU (no FMA contraction)
__device__ __forceinline__ float iou_rn(float ax1, float ay1, float ax2, float ay2, float aa,
                                        float bx1, float by1, float bx2, float by2, float ba)
{
    float ltx = fmaxf(ax1, bx1);
    float lty = fmaxf(ay1, by1);
    float rbx = fminf(ax2, bx2);
    float rby = fminf(ay2, by2);
    float wx  = fmaxf(__fsub_rn(rbx, ltx), 0.0f);
    float wy  = fmaxf(__fsub_rn(rby, lty), 0.0f);
    float inter = __fmul_rn(wx, wy);
    float uni   = __fsub_rn(__fadd_rn(aa, ba), inter);
    return __fdiv_rn(inter, fmaxf(uni, 1e-12f));
}

__global__ __launch_bounds__(NT, 2) void ssd_post_kernel(
    const float* __restrict__ loc,
    const float* __restrict__ conf,
    const float* __restrict__ priors,
    float* __restrict__ out)
{
    __shared__ ull    keys[NPAD];     // 32 KB
    __shared__ float4 sbox[NT];       // tile candidate boxes
    __shared__ float  sare[NT];       // tile candidate areas
    __shared__ float4 abox[TOPK];     // accepted boxes
    __shared__ float  aare[TOPK];     // accepted areas
    __shared__ int    salv[NWARP];    // per-warp alive ballots
    __shared__ int    s_nvalid;

    const int c    = blockIdx.x;
    const int b    = blockIdx.y;
    const int tid  = threadIdx.x;
    const int lane = tid & 31;
    const int wix  = tid >> 5;

    float* outp = out + (size_t)(b * NC + c) * (TOPK * 5);
    for (int k = tid; k < TOPK * 5; k += NT) outp[k] = 0.0f;
    if (c == 0) return;  // background class: zeros only

    if (tid == 0) s_nvalid = 0;
    __syncthreads();

    // ---- build sort keys: (sortable(score) << 32) | ~idx  (stable desc) ----
    const float* confb = conf + (size_t)b * NP * NC + c;
    int myValid = 0;
    #pragma unroll
    for (int w = 0; w < EPT; ++w) {
        int p = tid + w * NT;
        ull key = 0ULL;                               // padding: below everything
        if (p < NP) {
            float s = confb[(size_t)p * NC];
            bool v = (s > 0.01f);
            myValid += v ? 1 : 0;
            if (!v) s = __int_as_float(0xff800000);   // -inf: sorts after valid
            unsigned u = __float_as_uint(s);
            u = (u & 0x80000000u) ? ~u : (u | 0x80000000u);
            key = ((ull)u << 32) | (unsigned)(~p);
        }
        keys[SW(p)] = key;
    }
    #pragma unroll
    for (int o = 16; o > 0; o >>= 1)
        myValid += __shfl_down_sync(0xffffffffu, myValid, o);
    if (lane == 0 && myValid) atomicAdd(&s_nvalid, myValid);
    __syncthreads();

    // ---- bitonic sort, descending (register-fused) ----
    // fused register-local stages k = 2..16 (all strides < 16)
    {
        const int base = tid * EPT;
        ull r[EPT];
        #pragma unroll
        for (int m = 0; m < EPT; ++m) r[m] = keys[SW(base + m)];
        #pragma unroll
        for (int k = 2; k <= 16; k <<= 1) {
            #pragma unroll
            for (int j = k >> 1; j >= 1; j >>= 1) {
                #pragma unroll
                for (int m = 0; m < EPT; ++m)
                    if (!(m & j))
                        cexch(r[m], r[m | j], ((base + m) & k) == 0);
            }
        }
        #pragma unroll
        for (int m = 0; m < EPT; ++m) keys[SW(base + m)] = r[m];
    }
    __syncthreads();

    for (int k = 32; k <= NPAD; k <<= 1) {
        // smem substages: strides >= 16, pair-expanded (all threads active)
        for (int j = k >> 1; j >= 16; j >>= 1) {
            #pragma unroll
            for (int w = 0; w < NPAD / (2 * NT); ++w) {
                int p   = tid + w * NT;
                int i   = ((p & ~(j - 1)) << 1) | (p & (j - 1));
                int ixj = i | j;
                ull a  = keys[SW(i)];
                ull bb = keys[SW(ixj)];
                if (((i & k) == 0) ? (a < bb) : (a > bb)) {
                    keys[SW(i)] = bb; keys[SW(ixj)] = a;
                }
            }
            __syncthreads();
        }
        // register-local tail: strides 8,4,2,1 (uniform direction per thread)
        {
            const int  base = tid * EPT;
            const bool desc = ((base & k) == 0);
            ull r[EPT];
            #pragma unroll
            for (int m = 0; m < EPT; ++m) r[m] = keys[SW(base + m)];
            #pragma unroll
            for (int j = 8; j >= 1; j >>= 1) {
                #pragma unroll
                for (int m = 0; m < EPT; ++m)
                    if (!(m & j)) cexch(r[m], r[m | j], desc);
            }
            #pragma unroll
            for (int m = 0; m < EPT; ++m) keys[SW(base + m)] = r[m];
        }
        __syncthreads();
    }

    // ---- tiled candidate-driven NMS ----
    const int nvalid = s_nvalid;   // valid candidates form the sorted prefix
    const float* locb = loc + (size_t)b * NP * 4;

    int cnt = 0;                   // uniform register across all threads

    for (int tb = 0; tb < nvalid && cnt < TOPK; tb += NT) {
        const int j = tb + tid;
        ull key = keys[SW(j)];
        bool myAlive = (j < nvalid) && ((key >> 63) != 0ULL);

        // decode my candidate (exact reference op order) into regs + tile smem
        float mx1 = 0.f, my1 = 0.f, mx2 = 0.f, my2 = 0.f, mar = 0.f, ms = 0.f;
        if (myAlive) {
            int idx = (int)(~(unsigned)key);
            ms = __uint_as_float((unsigned)(key >> 32) & 0x7FFFFFFFu);
            float4 l  = *(const float4*)(locb + (size_t)idx * 4);
            float4 pr = *(const float4*)(priors + (size_t)idx * 4);
            float cx = __fadd_rn(pr.x, __fmul_rn(__fmul_rn(l.x, 0.1f), pr.z));
            float cy = __fadd_rn(pr.y, __fmul_rn(__fmul_rn(l.y, 0.1f), pr.w));
            float w  = __fmul_rn(pr.z, expf(__fmul_rn(l.z, 0.2f)));
            float hh = __fmul_rn(pr.w, expf(__fmul_rn(l.w, 0.2f)));
            mx1 = __fsub_rn(cx, __fmul_rn(0.5f, w));
            my1 = __fsub_rn(cy, __fmul_rn(0.5f, hh));
            mx2 = __fadd_rn(mx1, w);
            my2 = __fadd_rn(my1, hh);
            mar = __fmul_rn(__fsub_rn(mx2, mx1), __fsub_rn(my2, my1));
            sbox[tid] = make_float4(mx1, my1, mx2, my2);
            sare[tid] = mar;
        }

        // Phase A: branchless pipelined test vs accepted list; warp-vote
        // early-out every 16 boxes (dead lanes vote 'suppressed')
        {
            bool ov = !myAlive;
            int q = 0;
            while (q < cnt) {
                int qe = (q + 16 < cnt) ? (q + 16) : cnt;   // uniform
                #pragma unroll 4
                for (; q < qe; ++q) {
                    float4 ab = abox[q];
                    float ii = iou_rn(mx1, my1, mx2, my2, mar,
                                      ab.x, ab.y, ab.z, ab.w, aare[q]);
                    ov |= (ii > 0.45f);
                }
                if (__all_sync(0xffffffffu, ov)) break;   // whole warp settled
            }
            myAlive = myAlive && !ov;
        }
        unsigned wm = __ballot_sync(0xffffffffu, myAlive);
        if (lane == 0) salv[wix] = (int)wm;
        __syncthreads();   // publish sbox/sare/salv for the accept loop

        // Serial accept loop: ONE barrier per accept.
        // Every warp redundantly finds the first alive candidate from the 8
        // published ballot words (LDS+ballot+shfl+ffs). All branch decisions
        // read only barrier-published state => uniform.
        while (true) {
            int wv = (lane < NWARP) ? salv[lane] : 0;
            unsigned nz = __ballot_sync(0xffffffffu, wv != 0);
            if (nz == 0) break;                      // tile exhausted (uniform)
            int fw   = __ffs(nz) - 1;
            int word = __shfl_sync(0xffffffffu, wv, fw);
            int i    = (fw << 5) + __ffs(word) - 1;  // first alive candidate

            if (tid == i) {
                // accept my candidate as kept #cnt
                abox[cnt] = make_float4(mx1, my1, mx2, my2);
                aare[cnt] = mar;
                float* o = outp + cnt * 5;
                o[0] = ms; o[1] = mx1; o[2] = my1; o[3] = mx2; o[4] = my2;
                myAlive = false;
            } else if (myAlive) {
                // all alive threads have tid > i (i is the first alive)
                float4 ib = sbox[i];
                float ii = iou_rn(mx1, my1, mx2, my2, mar,
                                  ib.x, ib.y, ib.z, ib.w, sare[i]);
                if (ii > 0.45f) myAlive = false;
            }
            unsigned wm2 = __ballot_sync(0xffffffffu, myAlive);
            if (lane == 0) salv[wix] = (int)wm2;
            cnt++;                                   // uniform
            __syncthreads();                         // publish salv/abox/aare
            if (cnt >= TOPK) break;                  // uniform
        }
        __syncthreads();   // reconverge before next tile overwrites sbox/salv
    }
}

extern "C" void kernel_launch(void* const* d_in, const int* in_sizes, int n_in,
                              void* d_out, int out_size)
{
    const float* loc = nullptr;
    const float* conf = nullptr;
    const float* priors = nullptr;
    for (int i = 0; i < n_in; i++) {
        if (in_sizes[i] == 8 * NP * 4)       loc    = (const float*)d_in[i];
        else if (in_sizes[i] == 8 * NP * NC) conf   = (const float*)d_in[i];
        else if (in_sizes[i] == NP * 4)      priors = (const float*)d_in[i];
    }
    float* out = (float*)d_out;

    dim3 grid(NC, 8);
    ssd_post_kernel<<<grid, NT>>>(loc, conf, priors, out);
}